// round 11
// baseline (speedup 1.0000x reference)
#include <cuda_runtime.h>
#include <math.h>

#define NMAX 32
#define PMAX 8732
#define OMAX 16
#define ROWS 128
#define THREADS 256

// Scratch (no allocations). Zero at module load; re-zeroed by END of every run
// (reset discipline) so graph replays start from identical state.
__device__ unsigned long long g_pfo[NMAX * OMAX];
__device__ float g_ovl[NMAX * PMAX];
__device__ int   g_ofp[NMAX * PMAX];
__device__ float g_ce_neg[NMAX * PMAX];
__device__ int   g_npos[NMAX];
__device__ float g_sums[3];          // 0: loc_sum, 1: ce_pos_sum, 2: hard_neg_sum
__device__ int   g_iou_done[NMAX];
__device__ int   g_main_done[NMAX];
__device__ int   g_done;             // packed: low 8 bits finished count, upper np sum

template<int CT>
__global__ void __launch_bounds__(THREADS, 4)
k_mega(const float* __restrict__ locs, const float* __restrict__ scores,
       const float* __restrict__ boxes, const int* __restrict__ labels,
       const float* __restrict__ priors, float* __restrict__ out,
       int N, int P, int O, int Crt) {
    const int C = (CT > 0) ? CT : Crt;
    __shared__ float sh[ROWS * 81];          // staging; reused as topk buffer (P <= 10368)
    __shared__ unsigned hist[256];
    __shared__ float sb[OMAX * 4];
    __shared__ unsigned long long sbest[OMAX];
    __shared__ int s_force[OMAX];
    __shared__ float s_loc, s_cep;
    __shared__ int s_np, s_npv, s_flag;
    __shared__ unsigned s_prefix, s_kk;
    __shared__ float s_red[32];

    int tid = threadIdx.x, lane = tid & 31;
    int iouTiles  = (P + 255) >> 8;
    int mainTiles = (P + ROWS - 1) / ROWS;

    // ==================== Phase A: IoU + matching ====================
    for (int t = blockIdx.x; t < N * iouTiles; t += gridDim.x) {
        int n = t / iouTiles, tile = t - n * iouTiles;
        if (tid < O * 4) sb[tid] = boxes[(size_t)n * O * 4 + tid];
        if (tid < O) sbest[tid] = 0ull;
        __syncthreads();

        int p = tile * 256 + tid;
        int pc = p < P ? p : P - 1;              // clamp: duplicates are benign
        float4 pr4 = ((const float4*)priors)[pc];  // cx cy w h
        float px1 = pr4.x - pr4.z * 0.5f, py1 = pr4.y - pr4.w * 0.5f;
        float px2 = pr4.x + pr4.z * 0.5f, py2 = pr4.y + pr4.w * 0.5f;
        float pa  = pr4.z * pr4.w;

        float bestv = -1.0f; int besto = 0;
        #pragma unroll 4
        for (int o = 0; o < O; o++) {
            float bx1 = sb[o*4], by1 = sb[o*4+1], bx2 = sb[o*4+2], by2 = sb[o*4+3];
            float iw = fmaxf(fminf(px2, bx2) - fmaxf(px1, bx1), 0.0f);
            float ih = fmaxf(fminf(py2, by2) - fmaxf(py1, by1), 0.0f);
            float inter = iw * ih;
            float ba = (bx2 - bx1) * (by2 - by1);
            float v = __fdividef(inter, pa + ba - inter);
            if (v > bestv) { bestv = v; besto = o; }   // strict > => first occurrence
            // argmax over P: all max-lanes issue atomicMax; keys embed ~p so
            // ties resolve to smallest p, duplicates identical -> harmless.
            unsigned bits = __float_as_uint(v);        // v >= 0: bit order == value order
            unsigned maxb = __reduce_max_sync(0xffffffffu, bits);
            if (bits == maxb)
                atomicMax(&sbest[o], (((unsigned long long)maxb) << 32) |
                                     (unsigned long long)(0xffffffffu - (unsigned)pc));
        }
        g_ovl[(size_t)n * P + pc] = bestv;
        g_ofp[(size_t)n * P + pc] = besto;
        __syncthreads();
        if (tid < O) atomicMax(&g_pfo[n * O + tid], sbest[tid]);
        __threadfence();                 // all threads: order stores/atomics before counter
        __syncthreads();
        if (tid == 0) atomicAdd(&g_iou_done[n], 1);
    }

    // ==================== Phase B: CE + loc, then per-sample topK ====================
    for (int t = blockIdx.x; t < N * mainTiles; t += gridDim.x) {
        int n = t / mainTiles, chunk = t - n * mainTiles;

        if (tid == 0) {                  // wait for this sample's IoU phase
            while (atomicAdd(&g_iou_done[n], 0) < iouTiles) __nanosleep(64);
        }
        __syncthreads();

        int r0 = chunk * ROWS;
        int rows = P - r0; if (rows > ROWS) rows = ROWS;
        int elems = rows * C;
        const float* base = scores + ((size_t)n * P + r0) * C;

        if (tid == 0) { s_loc = 0.0f; s_cep = 0.0f; s_np = 0; }
        if (tid < O) {
            unsigned long long key = g_pfo[n * O + tid];
            s_force[tid] = (int)(0xffffffffu - (unsigned)(key & 0xffffffffu));
        }
        int e4 = elems >> 2;
        const float4* b4 = (const float4*)base;
        for (int i = tid; i < e4; i += THREADS) ((float4*)sh)[i] = b4[i];
        for (int i = (e4 << 2) + tid; i < elems; i += THREADS) sh[i] = base[i];
        __syncthreads();

        int p = r0 + tid;
        if (tid < rows) {
            const float* row = sh + tid * C;
            float s = 0.0f;
            if (CT == 81) {
                #pragma unroll
                for (int i = 0; i < 81; i++) s += __expf(row[i]);
            } else {
                for (int i = 0; i < C; i++) s += __expf(row[i]);
            }
            float lse = __logf(s);       // single-pass: inputs bounded, no overflow

            size_t idx = (size_t)n * P + p;
            float ovl = g_ovl[idx];
            int o = g_ofp[idx];
            #pragma unroll
            for (int oo = 0; oo < OMAX; oo++)
                if (oo < O && s_force[oo] == p) { o = oo; ovl = 1.0f; }  // last o wins
            int lbl = labels[n * O + o];
            int tc = (ovl < 0.5f) ? 0 : lbl;
            float ce = lse - row[tc];
            bool pos = (tc != 0);
            g_ce_neg[idx] = pos ? 0.0f : ce;
            if (pos) {
                float4 b  = ((const float4*)boxes)[n * O + o];
                float4 pr = ((const float4*)priors)[p];
                float cx = (b.x + b.z) * 0.5f, cy = (b.y + b.w) * 0.5f;
                float w = b.z - b.x, h = b.w - b.y;
                float g0 = (cx - pr.x) * 10.0f / pr.z;
                float g1 = (cy - pr.y) * 10.0f / pr.w;
                float g2 = __logf(w / pr.z) * 5.0f;
                float g3 = __logf(h / pr.w) * 5.0f;
                float4 pl = ((const float4*)locs)[idx];
                float l = fabsf(pl.x - g0) + fabsf(pl.y - g1) +
                          fabsf(pl.z - g2) + fabsf(pl.w - g3);
                atomicAdd(&s_loc, l);
                atomicAdd(&s_cep, ce);
                atomicAdd(&s_np, 1);
            }
        }
        __syncthreads();
        if (tid == 0 && s_np) {
            atomicAdd(&g_sums[0], s_loc);
            atomicAdd(&g_sums[1], s_cep);
            atomicAdd(&g_npos[n], s_np);
        }
        __threadfence();                 // all threads: ce_neg/sums visible before counter
        __syncthreads();
        if (tid == 0) {
            int d = atomicAdd(&g_main_done[n], 1);
            s_flag = (d == mainTiles - 1);
        }
        __syncthreads();

        if (s_flag) {
            // -------- fused per-sample topK (last finisher of sample n) --------
            for (int i = tid; i < P; i += THREADS) sh[i] = g_ce_neg[(size_t)n * P + i];
            if (tid == 0) s_npv = atomicAdd(&g_npos[n], 0);
            __syncthreads();             // all threads get np before any reset
            int np = s_npv;
            int K = 3 * np; if (K > P) K = P;
            if (tid == 0) {
                s_prefix = 0u; s_kk = (unsigned)K;
                g_npos[n] = 0; g_iou_done[n] = 0; g_main_done[n] = 0;  // per-sample reset
            }
            if (tid < O) g_pfo[n * O + tid] = 0ull;
            __syncthreads();

            if (K > 0) {
                for (int shift = 24; shift >= 0; shift -= 8) {
                    hist[tid & 255] = 0u;          // THREADS==256
                    __syncthreads();
                    unsigned prefix = s_prefix;
                    unsigned hm = (shift == 24) ? 0u : (0xffffffffu << (shift + 8));
                    for (int i = tid; i < P; i += THREADS) {
                        unsigned b = __float_as_uint(sh[i]);
                        if ((b & hm) == prefix) {
                            int bin = (b >> shift) & 255;
                            unsigned mask = __match_any_sync(__activemask(), bin);
                            if ((int)(__ffs(mask) - 1) == lane)
                                atomicAdd(&hist[bin], (unsigned)__popc(mask));
                        }
                    }
                    __syncthreads();
                    if (tid < 32) {      // warp 0: largest bin with suffix-count >= kk
                        unsigned kk = s_kk;
                        unsigned local[8]; unsigned lsum = 0;
                        #pragma unroll
                        for (int j = 0; j < 8; j++) { local[j] = hist[lane*8+j]; lsum += local[j]; }
                        unsigned pre = lsum;
                        #pragma unroll
                        for (int off = 1; off < 32; off <<= 1) {
                            unsigned v = __shfl_up_sync(0xffffffffu, pre, off);
                            if (lane >= off) pre += v;
                        }
                        unsigned total = __shfl_sync(0xffffffffu, pre, 31);
                        unsigned above_lane = total - pre;
                        int mybin = -1; unsigned myabove = 0;
                        unsigned run = above_lane;
                        #pragma unroll
                        for (int j = 7; j >= 0; j--) {
                            unsigned nrun = run + local[j];
                            if (mybin < 0 && nrun >= kk) { mybin = lane*8+j; myabove = run; }
                            run = nrun;
                        }
                        int selbin = (int)__reduce_max_sync(0xffffffffu,
                                        (unsigned)(mybin < 0 ? 0 : mybin));
                        int owner = selbin >> 3;
                        unsigned selabove = __shfl_sync(0xffffffffu, myabove, owner);
                        if (lane == 0) {
                            s_prefix = prefix | ((unsigned)selbin << shift);
                            s_kk = kk - selabove;
                        }
                    }
                    __syncthreads();
                }

                unsigned tbits = s_prefix;
                float tval = __uint_as_float(tbits);
                float sum = 0.0f; unsigned cnt = 0;
                for (int i = tid; i < P; i += THREADS) {
                    unsigned b = __float_as_uint(sh[i]);
                    if (b > tbits) { sum += sh[i]; cnt++; }
                }
                float fc = (float)cnt;
                #pragma unroll
                for (int off = 16; off; off >>= 1) {
                    sum += __shfl_xor_sync(0xffffffffu, sum, off);
                    fc  += __shfl_xor_sync(0xffffffffu, fc, off);
                }
                if ((tid & 31) == 0) { s_red[tid >> 5] = sum; hist[tid >> 5] = (unsigned)fc; }
                __syncthreads();
                if (tid < 32) {
                    float v = (lane < (THREADS >> 5)) ? s_red[lane] : 0.0f;
                    float c = (lane < (THREADS >> 5)) ? (float)hist[lane] : 0.0f;
                    #pragma unroll
                    for (int off = 16; off; off >>= 1) {
                        v += __shfl_xor_sync(0xffffffffu, v, off);
                        c += __shfl_xor_sync(0xffffffffu, c, off);
                    }
                    if (tid == 0) {
                        float total = v + ((float)K - c) * tval;
                        atomicAdd(&g_sums[2], total);
                    }
                }
            }
            __syncthreads();
            if (tid == 0) {
                __threadfence();
                int tt = atomicAdd(&g_done, (np << 8) + 1);
                if ((tt & 0xff) + 1 == N) {
                    __threadfence();
                    int npt = (tt >> 8) + np;
                    volatile float* vs = g_sums;
                    float fn = (float)npt;
                    float conf = (vs[2] + vs[1]) / fn;
                    float loc  = vs[0] / (4.0f * fn);
                    out[0] = conf + loc;
                    g_sums[0] = 0.0f; g_sums[1] = 0.0f; g_sums[2] = 0.0f;
                    g_done = 0;
                }
            }
            __syncthreads();
        }
    }
}

// ---------------------------------------------------------------------------
extern "C" void kernel_launch(void* const* d_in, const int* in_sizes, int n_in,
                              void* d_out, int out_size) {
    const float* locs   = (const float*)d_in[0];
    const float* scores = (const float*)d_in[1];
    const float* boxes  = (const float*)d_in[2];
    const int*   labels = (const int*)d_in[3];
    const float* priors = (const float*)d_in[4];

    int P = in_sizes[4] / 4;
    int N = in_sizes[0] / (4 * P);
    int C = in_sizes[1] / (N * P);
    int O = in_sizes[3] / N;

    // Co-resident grid: every block resident from launch -> spin-waits safe.
    int dev = 0, sms = 0, occ = 0;
    cudaGetDevice(&dev);
    cudaDeviceGetAttribute(&sms, cudaDevAttrMultiProcessorCount, dev);
    if (sms <= 0) sms = 148;
    if (C == 81)
        cudaOccupancyMaxActiveBlocksPerMultiprocessor(&occ, k_mega<81>, THREADS, 0);
    else
        cudaOccupancyMaxActiveBlocksPerMultiprocessor(&occ, k_mega<0>, THREADS, 0);
    if (occ <= 0) occ = 1;
    if (occ > 4) occ = 4;    // match __launch_bounds__ guarantee
    int grid = sms * occ;

    if (C == 81)
        k_mega<81><<<grid, THREADS>>>(locs, scores, boxes, labels, priors,
                                      (float*)d_out, N, P, O, C);
    else
        k_mega<0><<<grid, THREADS>>>(locs, scores, boxes, labels, priors,
                                     (float*)d_out, N, P, O, C);
}